// round 2
// baseline (speedup 1.0000x reference)
#include <cuda_runtime.h>
#include <cuda_fp16.h>
#include <cstdint>
#include <cstddef>

// Problem constants
#define Bsz  32
#define Rn   16384
#define Cn   16
#define Kdim 256      // OC*IC = 16*16
#define Od   16
#define RT   32       // r-tile per block in k_uhat
#define WPAD 260      // padded row stride (floats) for W smem tile

// ---------------- scratch (device globals; no allocation allowed) ----------
__device__ __half g_uhat[(size_t)Bsz * Cn * Rn * Od];   // 268 MB, layout [b][c][r][o]
__device__ float  g_logit[(size_t)Bsz * Cn * Rn];       // 33.5 MB, layout [b][c][r]
__device__ float  g_Wsum[Cn * Kdim];                    // sum over r of W
__device__ float  g_v0[Bsz * Cn * Od];
__device__ float  g_vsum[Bsz * Cn * Od];                // v0 + v1
__device__ float  g_sraw[Bsz * Cn * Od];                // un-normalized weighted sums
__device__ float  g_stats[Bsz * Cn * 2];                // {rowmax, sumexp} per (b,c)

// ---------------- helpers ---------------------------------------------------
__device__ __forceinline__ void store16h(__half* dst, const float* a) {
    union { uint4 u[2]; __half2 h[8]; } pk;
#pragma unroll
    for (int k = 0; k < 8; k++) pk.h[k] = __floats2half2_rn(a[2*k], a[2*k+1]);
    uint4* p = reinterpret_cast<uint4*>(dst);
    p[0] = pk.u[0];
    p[1] = pk.u[1];
}

// ---------------- K0: zero accumulators (per replay) -----------------------
__global__ void k_zero() {
    int i = blockIdx.x * blockDim.x + threadIdx.x;
    if (i < Cn * Kdim)      g_Wsum[i] = 0.f;
    if (i < Bsz * Cn * Od)  g_sraw[i] = 0.f;
}

// ---------------- K1: u_hat = einsum('rcoi,bci->brco'), store fp16 ---------
// Also accumulates Wsum[c,o,i] = sum_r W[r,c,o,i] (for s0 / v0).
// grid (Rn/RT, Cn), block 256. Thread t: bp = t>>4 (b-pair), rr = t&15 (r lane).
__global__ __launch_bounds__(256) void k_uhat(const float* __restrict__ W,
                                              const float* __restrict__ x) {
    __shared__ __align__(16) float Wst[RT * WPAD];
    __shared__ float xst[Bsz * 16];
    const int c  = blockIdx.y;
    const int r0 = blockIdx.x * RT;
    const int t  = threadIdx.x;

    // stage x[:, c, :]  (512 floats)
    for (int i = t; i < Bsz * 16; i += 256)
        xst[i] = x[((i >> 4) * Cn + c) * 16 + (i & 15)];
    // stage W tile: RT rows of 256 contiguous floats each
#pragma unroll
    for (int r = 0; r < RT; r++)
        Wst[r * WPAD + t] = W[((size_t)(r0 + r) * Cn + c) * Kdim + t];
    __syncthreads();

    // Wsum partial (column t of this tile summed over r)
    {
        float s = 0.f;
#pragma unroll
        for (int r = 0; r < RT; r++) s += Wst[r * WPAD + t];
        atomicAdd(&g_Wsum[c * Kdim + t], s);
    }

    const int bp = t >> 4, rr = t & 15;
    const int b0 = 2 * bp, b1 = 2 * bp + 1;
    float x0[16], x1[16];
#pragma unroll
    for (int i = 0; i < 16; i++) {
        x0[i] = xst[b0 * 16 + i];
        x1[i] = xst[b1 * 16 + i];
    }

#pragma unroll
    for (int rb = 0; rb < RT; rb += 16) {
        const int r = rb + rr;
        const float4* Wr = reinterpret_cast<const float4*>(&Wst[r * WPAD]);
        float a0[16], a1[16];
#pragma unroll
        for (int o = 0; o < 16; o++) {
            float s0 = 0.f, s1 = 0.f;
#pragma unroll
            for (int q = 0; q < 4; q++) {
                float4 w = Wr[o * 4 + q];
                s0 = fmaf(w.x, x0[4*q+0], s0); s0 = fmaf(w.y, x0[4*q+1], s0);
                s0 = fmaf(w.z, x0[4*q+2], s0); s0 = fmaf(w.w, x0[4*q+3], s0);
                s1 = fmaf(w.x, x1[4*q+0], s1); s1 = fmaf(w.y, x1[4*q+1], s1);
                s1 = fmaf(w.z, x1[4*q+2], s1); s1 = fmaf(w.w, x1[4*q+3], s1);
            }
            a0[o] = s0; a1[o] = s1;
        }
        const size_t rg = (size_t)(r0 + r);
        store16h(&g_uhat[(((size_t)b0 * Cn + c) * Rn + rg) * Od], a0);
        store16h(&g_uhat[(((size_t)b1 * Cn + c) * Rn + rg) * Od], a1);
    }
}

// ---------------- K2: v0 = squash((1/R) * Wsum . x) ------------------------
__global__ void k_v0(const float* __restrict__ x) {
    int t = blockIdx.x * blockDim.x + threadIdx.x;
    if (t >= Bsz * Cn) return;
    const int b = t >> 4, c = t & 15;
    float s[16], n2 = 0.f;
#pragma unroll
    for (int o = 0; o < 16; o++) {
        float acc = 0.f;
#pragma unroll
        for (int i = 0; i < 16; i++)
            acc = fmaf(g_Wsum[(c * 16 + o) * 16 + i], x[(b * Cn + c) * 16 + i], acc);
        acc *= (1.f / (float)Rn);
        s[o] = acc; n2 += acc * acc;
    }
    const float norm = sqrtf(n2);
    const float sc = norm / (1.f + n2);
#pragma unroll
    for (int o = 0; o < 16; o++) g_v0[t * 16 + o] = sc * s[o];
}

// ---------------- K3/K7: logits[b,c,r] = uhat[b,c,r,:] . v[b,c,:] ----------
// which == 0 -> v0   (gives b1 = uhat.v0)
// which == 1 -> vsum (gives b2 = uhat.(v0+v1) = b1 + uhat.v1)
__global__ __launch_bounds__(256) void k_logit(int which) {
    const int c = blockIdx.y, b = blockIdx.z;
    const size_t bcR = ((size_t)b * Cn + c) * Rn;
    const int r = blockIdx.x * 256 + threadIdx.x;
    __shared__ float vs[16];
    if (threadIdx.x < 16) {
        const float* v = which ? g_vsum : g_v0;
        vs[threadIdx.x] = v[(b * Cn + c) * 16 + threadIdx.x];
    }
    __syncthreads();
    uint4 raw[2];
    const uint4* up = reinterpret_cast<const uint4*>(&g_uhat[(bcR + r) * Od]);
    raw[0] = up[0]; raw[1] = up[1];
    const __half2* h = reinterpret_cast<const __half2*>(raw);
    float acc = 0.f;
#pragma unroll
    for (int k = 0; k < 8; k++) {
        float2 f = __half22float2(h[k]);
        acc = fmaf(f.x, vs[2*k], acc);
        acc = fmaf(f.y, vs[2*k+1], acc);
    }
    g_logit[bcR + r] = acc;
}

// ---------------- K4/K8: softmax stats over r per (b,c) --------------------
__global__ __launch_bounds__(256) void k_stats() {
    const int bc = blockIdx.x;
    const float* lg = g_logit + (size_t)bc * Rn;
    __shared__ float red[256];
    float mx = -1e30f;
    for (int i = threadIdx.x; i < Rn; i += 256) mx = fmaxf(mx, lg[i]);
    red[threadIdx.x] = mx; __syncthreads();
    for (int s = 128; s > 0; s >>= 1) {
        if (threadIdx.x < s) red[threadIdx.x] = fmaxf(red[threadIdx.x], red[threadIdx.x + s]);
        __syncthreads();
    }
    mx = red[0]; __syncthreads();
    float se = 0.f;
    for (int i = threadIdx.x; i < Rn; i += 256) se += __expf(lg[i] - mx);
    red[threadIdx.x] = se; __syncthreads();
    for (int s = 128; s > 0; s >>= 1) {
        if (threadIdx.x < s) red[threadIdx.x] += red[threadIdx.x + s];
        __syncthreads();
    }
    if (threadIdx.x == 0) { g_stats[bc * 2] = mx; g_stats[bc * 2 + 1] = red[0]; }
}

// ---------------- K5/K9: s_raw[b,c,o] += sum_r exp(logit-mx) * uhat --------
// grid (Rn/2048, Cn, Bsz), block 256, 8 r per thread
__global__ __launch_bounds__(256) void k_wsum() {
    const int c = blockIdx.y, b = blockIdx.z;
    const int bc = b * Cn + c;
    const size_t bcR = (size_t)bc * Rn;
    const float mx = g_stats[bc * 2];
    float acc[16];
#pragma unroll
    for (int o = 0; o < 16; o++) acc[o] = 0.f;
    const int rbase = blockIdx.x * (256 * 8) + threadIdx.x;
#pragma unroll
    for (int k = 0; k < 8; k++) {
        const int r = rbase + k * 256;
        const float w = __expf(g_logit[bcR + r] - mx);
        uint4 raw[2];
        const uint4* up = reinterpret_cast<const uint4*>(&g_uhat[(bcR + r) * Od]);
        raw[0] = up[0]; raw[1] = up[1];
        const __half2* h = reinterpret_cast<const __half2*>(raw);
#pragma unroll
        for (int j = 0; j < 8; j++) {
            float2 f = __half22float2(h[j]);
            acc[2*j]   = fmaf(w, f.x, acc[2*j]);
            acc[2*j+1] = fmaf(w, f.y, acc[2*j+1]);
        }
    }
    // warp reduce all 16 lanes' accumulators
#pragma unroll
    for (int o = 0; o < 16; o++) {
#pragma unroll
        for (int d = 16; d > 0; d >>= 1)
            acc[o] += __shfl_xor_sync(0xffffffffu, acc[o], d);
    }
    __shared__ float wacc[8][16];
    const int wid = threadIdx.x >> 5, lid = threadIdx.x & 31;
    if (lid == 0) {
#pragma unroll
        for (int o = 0; o < 16; o++) wacc[wid][o] = acc[o];
    }
    __syncthreads();
    if (threadIdx.x < 16) {
        float s = 0.f;
#pragma unroll
        for (int w2 = 0; w2 < 8; w2++) s += wacc[w2][threadIdx.x];
        atomicAdd(&g_sraw[bc * 16 + threadIdx.x], s);
    }
}

// ---------------- K6: v1 = squash(s1), vsum = v0+v1, reset s_raw -----------
__global__ void k_v1() {
    int t = blockIdx.x * blockDim.x + threadIdx.x;
    if (t >= Bsz * Cn) return;
    const float inv = 1.f / g_stats[t * 2 + 1];
    float s[16], n2 = 0.f;
#pragma unroll
    for (int o = 0; o < 16; o++) { s[o] = g_sraw[t * 16 + o] * inv; n2 += s[o] * s[o]; }
    const float norm = sqrtf(n2);
    const float sc = norm / (1.f + n2);
#pragma unroll
    for (int o = 0; o < 16; o++) {
        g_vsum[t * 16 + o] = g_v0[t * 16 + o] + sc * s[o];
        g_sraw[t * 16 + o] = 0.f;   // ready for s2 accumulation
    }
}

// ---------------- K10: out = squash(s2) ------------------------------------
__global__ void k_out(float* __restrict__ out) {
    int t = blockIdx.x * blockDim.x + threadIdx.x;
    if (t >= Bsz * Cn) return;
    const float inv = 1.f / g_stats[t * 2 + 1];
    float s[16], n2 = 0.f;
#pragma unroll
    for (int o = 0; o < 16; o++) { s[o] = g_sraw[t * 16 + o] * inv; n2 += s[o] * s[o]; }
    const float norm = sqrtf(n2);
    const float sc = norm / (1.f + n2);
#pragma unroll
    for (int o = 0; o < 16; o++) out[t * 16 + o] = sc * s[o];
}

// ---------------- launch ----------------------------------------------------
extern "C" void kernel_launch(void* const* d_in, const int* in_sizes, int n_in,
                              void* d_out, int out_size) {
    const float* x = (const float*)d_in[0];
    const float* W = (const float*)d_in[1];
    if (n_in >= 2 && in_sizes[0] > in_sizes[1]) {  // safety: x is 8192, W is 67M
        x = (const float*)d_in[1];
        W = (const float*)d_in[0];
    }
    float* out = (float*)d_out;

    k_zero<<<32, 256>>>();
    k_uhat<<<dim3(Rn / RT, Cn), 256>>>(W, x);
    k_v0<<<2, 256>>>(x);

    // iteration 1 (uses v0)
    k_logit<<<dim3(Rn / 256, Cn, Bsz), 256>>>(0);
    k_stats<<<Bsz * Cn, 256>>>();
    k_wsum<<<dim3(Rn / 2048, Cn, Bsz), 256>>>();
    k_v1<<<2, 256>>>();

    // iteration 2 (uses v0+v1)
    k_logit<<<dim3(Rn / 256, Cn, Bsz), 256>>>(1);
    k_stats<<<Bsz * Cn, 256>>>();
    k_wsum<<<dim3(Rn / 2048, Cn, Bsz), 256>>>();
    k_out<<<2, 256>>>(out);
}

// round 3
// speedup vs baseline: 1.2953x; 1.2953x over previous
#include <cuda_runtime.h>
#include <cuda_fp16.h>
#include <cstdint>
#include <cstddef>

// Problem constants
#define Bsz  32
#define Rn   16384
#define Cn   16
#define Kdim 256      // OC*IC = 16*16
#define Od   16
#define RT   32       // r-tile per block in k_uhat
#define WPAD 260      // padded row stride (floats) for W smem tile
#define RPT  16       // r per thread in fused routing kernel

// ---------------- scratch (device globals; no allocation allowed) ----------
__device__ __half g_uhat[(size_t)Bsz * Cn * Rn * Od];   // 268 MB, layout [b][c][r][o]
__device__ float  g_Wsum[Cn * Kdim];                    // sum over r of W
__device__ float  g_v0[Bsz * Cn * Od];
__device__ float  g_vsum[Bsz * Cn * Od];                // v0 + v1
__device__ float  g_sraw[Bsz * Cn * Od];                // un-normalized weighted sums
__device__ float  g_sumexp[Bsz * Cn];                   // sum of exp(logit) per (b,c)

// ---------------- helpers ---------------------------------------------------
__device__ __forceinline__ void store16h(__half* dst, const float* a) {
    union { uint4 u[2]; __half2 h[8]; } pk;
#pragma unroll
    for (int k = 0; k < 8; k++) pk.h[k] = __floats2half2_rn(a[2*k], a[2*k+1]);
    uint4* p = reinterpret_cast<uint4*>(dst);
    p[0] = pk.u[0];
    p[1] = pk.u[1];
}

// ---------------- K0: zero accumulators (per replay) -----------------------
__global__ void k_zero() {
    int i = blockIdx.x * blockDim.x + threadIdx.x;
    if (i < Cn * Kdim)      g_Wsum[i] = 0.f;
    if (i < Bsz * Cn * Od)  g_sraw[i] = 0.f;
    if (i < Bsz * Cn)       g_sumexp[i] = 0.f;
}

// ---------------- K1: u_hat = einsum('rcoi,bci->brco'), store fp16 ---------
// Also accumulates Wsum[c,o,i] = sum_r W[r,c,o,i] (for s0 / v0).
// grid (Rn/RT, Cn), block 256. Thread t: bp = t>>4 (b-pair), rr = t&15 (r lane).
__global__ __launch_bounds__(256) void k_uhat(const float* __restrict__ W,
                                              const float* __restrict__ x) {
    __shared__ __align__(16) float Wst[RT * WPAD];
    __shared__ float xst[Bsz * 16];
    const int c  = blockIdx.y;
    const int r0 = blockIdx.x * RT;
    const int t  = threadIdx.x;

    // stage x[:, c, :]  (512 floats)
    for (int i = t; i < Bsz * 16; i += 256)
        xst[i] = x[((i >> 4) * Cn + c) * 16 + (i & 15)];
    // stage W tile: RT rows of 256 contiguous floats each
#pragma unroll
    for (int r = 0; r < RT; r++)
        Wst[r * WPAD + t] = W[((size_t)(r0 + r) * Cn + c) * Kdim + t];
    __syncthreads();

    // Wsum partial (column t of this tile summed over r)
    {
        float s = 0.f;
#pragma unroll
        for (int r = 0; r < RT; r++) s += Wst[r * WPAD + t];
        atomicAdd(&g_Wsum[c * Kdim + t], s);
    }

    const int bp = t >> 4, rr = t & 15;
    const int b0 = 2 * bp, b1 = 2 * bp + 1;
    float x0[16], x1[16];
#pragma unroll
    for (int i = 0; i < 16; i++) {
        x0[i] = xst[b0 * 16 + i];
        x1[i] = xst[b1 * 16 + i];
    }

#pragma unroll
    for (int rb = 0; rb < RT; rb += 16) {
        const int r = rb + rr;
        const float4* Wr = reinterpret_cast<const float4*>(&Wst[r * WPAD]);
        float a0[16], a1[16];
#pragma unroll
        for (int o = 0; o < 16; o++) {
            float s0 = 0.f, s1 = 0.f;
#pragma unroll
            for (int q = 0; q < 4; q++) {
                float4 w = Wr[o * 4 + q];
                s0 = fmaf(w.x, x0[4*q+0], s0); s0 = fmaf(w.y, x0[4*q+1], s0);
                s0 = fmaf(w.z, x0[4*q+2], s0); s0 = fmaf(w.w, x0[4*q+3], s0);
                s1 = fmaf(w.x, x1[4*q+0], s1); s1 = fmaf(w.y, x1[4*q+1], s1);
                s1 = fmaf(w.z, x1[4*q+2], s1); s1 = fmaf(w.w, x1[4*q+3], s1);
            }
            a0[o] = s0; a1[o] = s1;
        }
        const size_t rg = (size_t)(r0 + r);
        store16h(&g_uhat[(((size_t)b0 * Cn + c) * Rn + rg) * Od], a0);
        store16h(&g_uhat[(((size_t)b1 * Cn + c) * Rn + rg) * Od], a1);
    }
}

// ---------------- K2: v0 = squash((1/R) * Wsum . x) ------------------------
__global__ void k_v0(const float* __restrict__ x) {
    int t = blockIdx.x * blockDim.x + threadIdx.x;
    if (t >= Bsz * Cn) return;
    const int b = t >> 4, c = t & 15;
    float s[16], n2 = 0.f;
#pragma unroll
    for (int o = 0; o < 16; o++) {
        float acc = 0.f;
#pragma unroll
        for (int i = 0; i < 16; i++)
            acc = fmaf(g_Wsum[(c * 16 + o) * 16 + i], x[(b * Cn + c) * 16 + i], acc);
        acc *= (1.f / (float)Rn);
        s[o] = acc; n2 += acc * acc;
    }
    const float norm = sqrtf(n2);
    const float sc = norm / (1.f + n2);
#pragma unroll
    for (int o = 0; o < 16; o++) g_v0[t * 16 + o] = sc * s[o];
}

// ---------------- K3: fused routing pass ------------------------------------
// One streaming pass over u_hat per iteration:
//   logit = uhat . v ;  e = exp(logit)  (no max-shift: logits bounded, fp32 safe)
//   sraw[b,c,:] += e * uhat ;  sumexp[b,c] += e
// grid (Rn/(256*RPT), Cn, Bsz), block 256.
__global__ __launch_bounds__(256) void k_route(const float* __restrict__ vsrc) {
    const int c = blockIdx.y, b = blockIdx.z;
    const int bc = b * Cn + c;
    const size_t bcR = (size_t)bc * Rn;

    __shared__ float vsm[16];
    if (threadIdx.x < 16) vsm[threadIdx.x] = vsrc[bc * 16 + threadIdx.x];
    __syncthreads();
    float vreg[16];
#pragma unroll
    for (int i = 0; i < 16; i++) vreg[i] = vsm[i];

    float acc[16], lsum = 0.f;
#pragma unroll
    for (int o = 0; o < 16; o++) acc[o] = 0.f;

    const int rbase = blockIdx.x * (256 * RPT) + threadIdx.x;
#pragma unroll 4
    for (int k = 0; k < RPT; k++) {
        const int r = rbase + k * 256;
        uint4 raw[2];
        const uint4* up = reinterpret_cast<const uint4*>(&g_uhat[(bcR + r) * Od]);
        raw[0] = up[0]; raw[1] = up[1];
        const __half2* h = reinterpret_cast<const __half2*>(raw);
        float f[16];
#pragma unroll
        for (int j = 0; j < 8; j++) {
            float2 t2 = __half22float2(h[j]);
            f[2*j] = t2.x; f[2*j+1] = t2.y;
        }
        float lg = 0.f;
#pragma unroll
        for (int j = 0; j < 16; j++) lg = fmaf(f[j], vreg[j], lg);
        const float w = __expf(lg);
        lsum += w;
#pragma unroll
        for (int j = 0; j < 16; j++) acc[j] = fmaf(w, f[j], acc[j]);
    }

    // warp reduce 17 values
#pragma unroll
    for (int o = 0; o < 16; o++) {
#pragma unroll
        for (int d = 16; d > 0; d >>= 1)
            acc[o] += __shfl_xor_sync(0xffffffffu, acc[o], d);
    }
#pragma unroll
    for (int d = 16; d > 0; d >>= 1)
        lsum += __shfl_xor_sync(0xffffffffu, lsum, d);

    __shared__ float wacc[8][17];
    const int wid = threadIdx.x >> 5, lid = threadIdx.x & 31;
    if (lid == 0) {
#pragma unroll
        for (int o = 0; o < 16; o++) wacc[wid][o] = acc[o];
        wacc[wid][16] = lsum;
    }
    __syncthreads();
    if (threadIdx.x < 17) {
        float s = 0.f;
#pragma unroll
        for (int w2 = 0; w2 < 8; w2++) s += wacc[w2][threadIdx.x];
        if (threadIdx.x < 16) atomicAdd(&g_sraw[bc * 16 + threadIdx.x], s);
        else                  atomicAdd(&g_sumexp[bc], s);
    }
}

// ---------------- K4: v1 = squash(s1), vsum = v0+v1, reset accumulators ----
__global__ void k_v1() {
    int t = blockIdx.x * blockDim.x + threadIdx.x;
    if (t >= Bsz * Cn) return;
    const float inv = 1.f / g_sumexp[t];
    float s[16], n2 = 0.f;
#pragma unroll
    for (int o = 0; o < 16; o++) { s[o] = g_sraw[t * 16 + o] * inv; n2 += s[o] * s[o]; }
    const float norm = sqrtf(n2);
    const float sc = norm / (1.f + n2);
#pragma unroll
    for (int o = 0; o < 16; o++) {
        g_vsum[t * 16 + o] = g_v0[t * 16 + o] + sc * s[o];
        g_sraw[t * 16 + o] = 0.f;   // ready for iteration-2 accumulation
    }
    g_sumexp[t] = 0.f;
}

// ---------------- K5: out = squash(s2) ------------------------------------
__global__ void k_out(float* __restrict__ out) {
    int t = blockIdx.x * blockDim.x + threadIdx.x;
    if (t >= Bsz * Cn) return;
    const float inv = 1.f / g_sumexp[t];
    float s[16], n2 = 0.f;
#pragma unroll
    for (int o = 0; o < 16; o++) { s[o] = g_sraw[t * 16 + o] * inv; n2 += s[o] * s[o]; }
    const float norm = sqrtf(n2);
    const float sc = norm / (1.f + n2);
#pragma unroll
    for (int o = 0; o < 16; o++) out[t * 16 + o] = sc * s[o];
}

// ---------------- launch ----------------------------------------------------
extern "C" void kernel_launch(void* const* d_in, const int* in_sizes, int n_in,
                              void* d_out, int out_size) {
    const float* x = (const float*)d_in[0];
    const float* W = (const float*)d_in[1];
    if (n_in >= 2 && in_sizes[0] > in_sizes[1]) {  // safety: x is 8192, W is 67M
        x = (const float*)d_in[1];
        W = (const float*)d_in[0];
    }
    float* out = (float*)d_out;

    float* d_v0   = nullptr;
    float* d_vsum = nullptr;
    cudaGetSymbolAddress((void**)&d_v0,   g_v0);
    cudaGetSymbolAddress((void**)&d_vsum, g_vsum);

    k_zero<<<32, 256>>>();
    k_uhat<<<dim3(Rn / RT, Cn), 256>>>(W, x);
    k_v0<<<2, 256>>>(x);

    // iteration 1 (uses v0)
    k_route<<<dim3(Rn / (256 * RPT), Cn, Bsz), 256>>>(d_v0);
    k_v1<<<2, 256>>>();

    // iteration 2 (uses v0+v1)
    k_route<<<dim3(Rn / (256 * RPT), Cn, Bsz), 256>>>(d_vsum);
    k_out<<<2, 256>>>(out);
}

// round 4
// speedup vs baseline: 1.7904x; 1.3822x over previous
#include <cuda_runtime.h>
#include <cuda_fp16.h>
#include <cstdint>
#include <cstddef>

// Problem constants
#define Bsz  32
#define Rn   16384
#define Cn   16
#define Od   16

#define WARPS 8
#define RPW   16    // r per warp in k_route_mma
#define RBLK  (WARPS * RPW)   // 128 r per block

// ---------------- scratch (device globals; no allocation allowed) ----------
__device__ float g_Wsum[Cn * 256];        // sum over r of W  [c][o][i]
__device__ float g_v0[Bsz * Cn * Od];
__device__ float g_vsum[Bsz * Cn * Od];   // v0 + v1
__device__ float g_sraw[Bsz * Cn * Od];   // un-normalized weighted sums
__device__ float g_sumexp[Bsz * Cn];      // sum of exp(logit) per (b,c)

// ---------------- helpers ---------------------------------------------------
__device__ __forceinline__ uint32_t packh2(float a, float b) {
    __half2 h = __floats2half2_rn(a, b);
    return *reinterpret_cast<uint32_t*>(&h);
}

__device__ __forceinline__ void mma16816(float* d, const uint32_t* a,
                                         uint32_t b0, uint32_t b1) {
    asm volatile(
        "mma.sync.aligned.m16n8k16.row.col.f32.f16.f16.f32 "
        "{%0,%1,%2,%3}, {%4,%5,%6,%7}, {%8,%9}, {%10,%11,%12,%13};\n"
        : "=f"(d[0]), "=f"(d[1]), "=f"(d[2]), "=f"(d[3])
        : "r"(a[0]), "r"(a[1]), "r"(a[2]), "r"(a[3]),
          "r"(b0), "r"(b1),
          "f"(0.f), "f"(0.f), "f"(0.f), "f"(0.f));
}

// ---------------- K0: zero accumulators (per replay) -----------------------
__global__ void k_zero() {
    int i = blockIdx.x * blockDim.x + threadIdx.x;
    if (i < Cn * 256)       g_Wsum[i] = 0.f;
    if (i < Bsz * Cn * Od)  g_sraw[i] = 0.f;
    if (i < Bsz * Cn)       g_sumexp[i] = 0.f;
}

// ---------------- K1: Wsum[c,o,i] = sum_r W[r,c,o,i]  (pure stream) --------
// grid (64, Cn), block 256. Block (rb, c) reduces 256 r's.
__global__ __launch_bounds__(256) void k_wsum(const float* __restrict__ W) {
    const int c = blockIdx.y;
    const int t = threadIdx.x;
    const size_t rbase = (size_t)blockIdx.x * 256;
    float a0 = 0.f, a1 = 0.f, a2 = 0.f, a3 = 0.f;
#pragma unroll 4
    for (int k = 0; k < 256; k += 4) {
        a0 += W[((rbase + k + 0) * Cn + c) * 256 + t];
        a1 += W[((rbase + k + 1) * Cn + c) * 256 + t];
        a2 += W[((rbase + k + 2) * Cn + c) * 256 + t];
        a3 += W[((rbase + k + 3) * Cn + c) * 256 + t];
    }
    atomicAdd(&g_Wsum[c * 256 + t], (a0 + a1) + (a2 + a3));
}

// ---------------- K2: v0 = squash((1/R) * Wsum . x) ------------------------
__global__ void k_v0(const float* __restrict__ x) {
    int t = blockIdx.x * blockDim.x + threadIdx.x;
    if (t >= Bsz * Cn) return;
    const int b = t >> 4, c = t & 15;
    float s[16], n2 = 0.f;
#pragma unroll
    for (int o = 0; o < 16; o++) {
        float acc = 0.f;
#pragma unroll
        for (int i = 0; i < 16; i++)
            acc = fmaf(g_Wsum[(c * 16 + o) * 16 + i], x[(b * Cn + c) * 16 + i], acc);
        acc *= (1.f / (float)Rn);
        s[o] = acc; n2 += acc * acc;
    }
    const float norm = sqrtf(n2);
    const float sc = norm / (1.f + n2);
#pragma unroll
    for (int o = 0; o < 16; o++) g_v0[t * 16 + o] = sc * s[o];
}

// ---------------- K3: fused routing pass with HMMA recompute ----------------
// Per warp, per r:
//   B-frags  <- W[r][c][:][:]   (1KB fp32, 4x LDG.64/lane, cvt fp16)
//   u_hat    =  mma(A=x fp16, B=W fp16)  -> 16 fp32 per lane: (b,o) grid
//   logit[b] =  quad-reduce( u . v )  ;  w = exp(logit)
//   acc[b,o] += w * u ;  esum[b] += w
// grid (Rn/RBLK, Cn), block 256 (8 warps).
__global__ __launch_bounds__(256) void k_route_mma(const float* __restrict__ W,
                                                   const float* __restrict__ x,
                                                   const float* __restrict__ vsrc) {
    const int c    = blockIdx.y;
    const int tid  = threadIdx.x;
    const int wid  = tid >> 5;
    const int lane = tid & 31;
    const int g    = lane >> 2;   // group id
    const int tg   = lane & 3;    // thread in group

    // ---- A fragments from x (fp32 -> fp16). M dim = b, K dim = i. ----
    // a0: row g      cols 2t,2t+1 | a1: row g+8 same | a2: row g  cols 2t+8.. | a3: row g+8 cols 2t+8..
    uint32_t A[8];
#pragma unroll
    for (int mt = 0; mt < 2; mt++) {
        const int b_lo = g + mt * 16, b_hi = g + 8 + mt * 16;
#pragma unroll
        for (int kh = 0; kh < 2; kh++) {
            float2 lo = *reinterpret_cast<const float2*>(&x[(b_lo * Cn + c) * 16 + 2 * tg + kh * 8]);
            float2 hi = *reinterpret_cast<const float2*>(&x[(b_hi * Cn + c) * 16 + 2 * tg + kh * 8]);
            A[mt * 4 + kh * 2 + 0] = packh2(lo.x, lo.y);
            A[mt * 4 + kh * 2 + 1] = packh2(hi.x, hi.y);
        }
    }

    // ---- v values for this lane's 16 (b,o) positions (fp32) ----
    // b(bi) = g + 8*bi ; o(oj) = 2*tg + (oj&1) + 8*(oj>>1)
    float vv[16];
#pragma unroll
    for (int bi = 0; bi < 4; bi++) {
        const int b = g + 8 * bi;
#pragma unroll
        for (int oj = 0; oj < 4; oj++) {
            const int o = 2 * tg + (oj & 1) + 8 * (oj >> 1);
            vv[bi * 4 + oj] = vsrc[(b * Cn + c) * 16 + o];
        }
    }

    float acc[16], esum[4];
#pragma unroll
    for (int j = 0; j < 16; j++) acc[j] = 0.f;
#pragma unroll
    for (int j = 0; j < 4; j++) esum[j] = 0.f;

    const int r0 = blockIdx.x * RBLK + wid * RPW;

#pragma unroll 2
    for (int k = 0; k < RPW; k++) {
        const size_t rw = (size_t)(r0 + k);
        const float2* Wp = reinterpret_cast<const float2*>(&W[(rw * Cn + c) * 256]);
        // B frags: n-tile0 = o 0-7 (rows g), n-tile1 = o 8-15 (rows g+8)
        float2 f0 = Wp[g * 8 + tg];             // W[o=g   ][i=2t..2t+1]
        float2 f1 = Wp[g * 8 + tg + 4];         // W[o=g   ][i=2t+8..]
        float2 f2 = Wp[(g + 8) * 8 + tg];       // W[o=g+8 ][i=2t..]
        float2 f3 = Wp[(g + 8) * 8 + tg + 4];   // W[o=g+8 ][i=2t+8..]
        uint32_t B00 = packh2(f0.x, f0.y), B01 = packh2(f1.x, f1.y);
        uint32_t B10 = packh2(f2.x, f2.y), B11 = packh2(f3.x, f3.y);

        float d[16];
        mma16816(d + 0,  A,     B00, B01);   // b 0-15,  o 0-7
        mma16816(d + 4,  A,     B10, B11);   // b 0-15,  o 8-15
        mma16816(d + 8,  A + 4, B00, B01);   // b 16-31, o 0-7
        mma16816(d + 12, A + 4, B10, B11);   // b 16-31, o 8-15
        // u[bi][oj] = d[(bi>>1)*8 + (oj>>1)*4 + (bi&1)*2 + (oj&1)]

        float p[4];
#pragma unroll
        for (int bi = 0; bi < 4; bi++) {
            float s = 0.f;
#pragma unroll
            for (int oj = 0; oj < 4; oj++) {
                const int di = ((bi >> 1) << 3) + ((oj >> 1) << 2) + ((bi & 1) << 1) + (oj & 1);
                s = fmaf(d[di], vv[bi * 4 + oj], s);
            }
            p[bi] = s;
        }
        // quad reduce (lanes 4g..4g+3 hold disjoint o-subsets)
#pragma unroll
        for (int bi = 0; bi < 4; bi++) {
            p[bi] += __shfl_xor_sync(0xffffffffu, p[bi], 1);
            p[bi] += __shfl_xor_sync(0xffffffffu, p[bi], 2);
        }
#pragma unroll
        for (int bi = 0; bi < 4; bi++) {
            const float w = __expf(p[bi]);
            esum[bi] += w;
#pragma unroll
            for (int oj = 0; oj < 4; oj++) {
                const int di = ((bi >> 1) << 3) + ((oj >> 1) << 2) + ((bi & 1) << 1) + (oj & 1);
                acc[bi * 4 + oj] = fmaf(w, d[di], acc[bi * 4 + oj]);
            }
        }
    }

    // ---- block reduction: lane mapping identical across warps ----
    __shared__ float s_acc[32][17];   // [lane][j], padded vs bank conflicts
    __shared__ float s_es[32];        // [b]
    for (int i = tid; i < 32 * 17; i += 256) (&s_acc[0][0])[i] = 0.f;
    if (tid < 32) s_es[tid] = 0.f;
    __syncthreads();

#pragma unroll
    for (int j = 0; j < 16; j++) atomicAdd(&s_acc[lane][j], acc[j]);
    if (tg == 0) {
#pragma unroll
        for (int bi = 0; bi < 4; bi++) atomicAdd(&s_es[g + 8 * bi], esum[bi]);
    }
    __syncthreads();

    // ---- global accumulation ----
    for (int v = tid; v < 512; v += 256) {
        const int ln = v >> 4, j = v & 15;
        const int b = (ln >> 2) + (j >> 2) * 8;
        const int o = ((ln & 3) << 1) + (j & 1) + ((j >> 1) & 1) * 8;
        atomicAdd(&g_sraw[(b * Cn + c) * 16 + o], s_acc[ln][j]);
    }
    if (tid < 32) atomicAdd(&g_sumexp[tid * Cn + c], s_es[tid]);
}

// ---------------- K4: v1 = squash(s1), vsum = v0+v1, reset accumulators ----
__global__ void k_v1() {
    int t = blockIdx.x * blockDim.x + threadIdx.x;
    if (t >= Bsz * Cn) return;
    const float inv = 1.f / g_sumexp[t];
    float s[16], n2 = 0.f;
#pragma unroll
    for (int o = 0; o < 16; o++) { s[o] = g_sraw[t * 16 + o] * inv; n2 += s[o] * s[o]; }
    const float norm = sqrtf(n2);
    const float sc = norm / (1.f + n2);
#pragma unroll
    for (int o = 0; o < 16; o++) {
        g_vsum[t * 16 + o] = g_v0[t * 16 + o] + sc * s[o];
        g_sraw[t * 16 + o] = 0.f;
    }
    g_sumexp[t] = 0.f;
}

// ---------------- K5: out = squash(s2) --------------------------------------
__global__ void k_out(float* __restrict__ out) {
    int t = blockIdx.x * blockDim.x + threadIdx.x;
    if (t >= Bsz * Cn) return;
    const float inv = 1.f / g_sumexp[t];
    float s[16], n2 = 0.f;
#pragma unroll
    for (int o = 0; o < 16; o++) { s[o] = g_sraw[t * 16 + o] * inv; n2 += s[o] * s[o]; }
    const float norm = sqrtf(n2);
    const float sc = norm / (1.f + n2);
#pragma unroll
    for (int o = 0; o < 16; o++) out[t * 16 + o] = sc * s[o];
}

// ---------------- launch ----------------------------------------------------
extern "C" void kernel_launch(void* const* d_in, const int* in_sizes, int n_in,
                              void* d_out, int out_size) {
    const float* x = (const float*)d_in[0];
    const float* W = (const float*)d_in[1];
    if (n_in >= 2 && in_sizes[0] > in_sizes[1]) {  // safety: x is 8192, W is 67M
        x = (const float*)d_in[1];
        W = (const float*)d_in[0];
    }
    float* out = (float*)d_out;

    float* d_v0   = nullptr;
    float* d_vsum = nullptr;
    cudaGetSymbolAddress((void**)&d_v0,   g_v0);
    cudaGetSymbolAddress((void**)&d_vsum, g_vsum);

    k_zero<<<32, 256>>>();
    k_wsum<<<dim3(Rn / 256, Cn), 256>>>(W);
    k_v0<<<2, 256>>>(x);

    // iteration 1 (uses v0)
    k_route_mma<<<dim3(Rn / RBLK, Cn), 256>>>(W, x, d_v0);
    k_v1<<<2, 256>>>();

    // iteration 2 (uses v0+v1)
    k_route_mma<<<dim3(Rn / RBLK, Cn), 256>>>(W, x, d_vsum);
    k_out<<<2, 256>>>(out);
}

// round 5
// speedup vs baseline: 2.0101x; 1.1227x over previous
#include <cuda_runtime.h>
#include <cuda_fp16.h>
#include <cstdint>
#include <cstddef>

// Problem constants
#define Bsz  32
#define Rn   16384
#define Cn   16
#define Od   16

#define WARPS 8
#define RPW   32                 // r per warp in k_route_mma
#define RBLK  (WARPS * RPW)      // 256 r per block
#define PR    64                 // r rows per k_prep block

// ---------------- scratch (device globals; no allocation allowed) ----------
__device__ uint4 g_Wh4[(size_t)Rn * Cn * 32];   // 134 MB fp16 W, fragment-packed
__device__ float g_Wsum[Cn * 256];              // sum over r of W  [c][o][i]
__device__ float g_v0[Bsz * Cn * Od];
__device__ float g_vsum[Bsz * Cn * Od];         // v0 + v1
__device__ float g_sraw[Bsz * Cn * Od];         // un-normalized weighted sums
__device__ float g_sumexp[Bsz * Cn];            // sum of exp(logit) per (b,c)

// ---------------- helpers ---------------------------------------------------
__device__ __forceinline__ uint32_t packh2(float a, float b) {
    __half2 h = __floats2half2_rn(a, b);
    return *reinterpret_cast<uint32_t*>(&h);
}

__device__ __forceinline__ void mma16816(float* d, const uint32_t* a,
                                         uint32_t b0, uint32_t b1) {
    asm volatile(
        "mma.sync.aligned.m16n8k16.row.col.f32.f16.f16.f32 "
        "{%0,%1,%2,%3}, {%4,%5,%6,%7}, {%8,%9}, {%10,%11,%12,%13};\n"
        : "=f"(d[0]), "=f"(d[1]), "=f"(d[2]), "=f"(d[3])
        : "r"(a[0]), "r"(a[1]), "r"(a[2]), "r"(a[3]),
          "r"(b0), "r"(b1),
          "f"(0.f), "f"(0.f), "f"(0.f), "f"(0.f));
}

// ---------------- K0: zero accumulators (per replay) -----------------------
__global__ void k_zero() {
    int i = blockIdx.x * blockDim.x + threadIdx.x;
    if (i < Cn * 256)       g_Wsum[i] = 0.f;
    if (i < Bsz * Cn * Od)  g_sraw[i] = 0.f;
    if (i < Bsz * Cn)       g_sumexp[i] = 0.f;
}

// ---------------- K1: prep — convert W to packed fp16 frags + Wsum ---------
// grid (Rn/PR, Cn), block 256 (8 warps). Per iter: stage 8 (r,c)-rows (8KB),
// accumulate column sums in registers, warp w converts row w to fragment order.
// Fragment layout per (c,r): lane l (g=l>>2, tg=l&3) owns uint4
//   { h2(W[o=g][2tg],W[o=g][2tg+1]), h2(W[g][2tg+8],W[g][2tg+9]),
//     h2(W[g+8][2tg],...),           h2(W[g+8][2tg+8],...) }
// stored at g_Wh4[(c*Rn + r)*32 + l]  (c-major so route reads are contiguous in r)
__global__ __launch_bounds__(256) void k_prep(const float* __restrict__ W) {
    __shared__ float sm[8 * 256];
    const int c  = blockIdx.y;
    const int r0 = blockIdx.x * PR;
    const int t  = threadIdx.x;
    const int wid = t >> 5, lane = t & 31;
    const int g = lane >> 2, tg = lane & 3;
    float wsum = 0.f;

    for (int it = 0; it < PR / 8; it++) {
        __syncthreads();   // previous tile fully consumed
#pragma unroll
        for (int h = 0; h < 2; h++) {
            const int v   = t + h * 256;   // float4 index within 8x256 tile
            const int row = v >> 6;
            const int c4  = v & 63;
            float4 f = *reinterpret_cast<const float4*>(
                &W[(((size_t)(r0 + it * 8 + row)) * Cn + c) * 256 + c4 * 4]);
            *reinterpret_cast<float4*>(&sm[v * 4]) = f;
        }
        __syncthreads();
        // column partial sums (conflict-free: lane-consecutive addresses)
#pragma unroll
        for (int k = 0; k < 8; k++) wsum += sm[k * 256 + t];
        // conversion: warp wid handles row wid of this tile
        {
            const float* row = &sm[wid * 256];
            float2 f0 = *reinterpret_cast<const float2*>(&row[g * 16 + 2 * tg]);
            float2 f1 = *reinterpret_cast<const float2*>(&row[g * 16 + 2 * tg + 8]);
            float2 f2 = *reinterpret_cast<const float2*>(&row[(g + 8) * 16 + 2 * tg]);
            float2 f3 = *reinterpret_cast<const float2*>(&row[(g + 8) * 16 + 2 * tg + 8]);
            uint4 o;
            o.x = packh2(f0.x, f0.y); o.y = packh2(f1.x, f1.y);
            o.z = packh2(f2.x, f2.y); o.w = packh2(f3.x, f3.y);
            const size_t r = (size_t)(r0 + it * 8 + wid);
            g_Wh4[((size_t)c * Rn + r) * 32 + lane] = o;
        }
    }
    atomicAdd(&g_Wsum[c * 256 + t], wsum);
}

// ---------------- K2: v0 = squash((1/R) * Wsum . x) ------------------------
__global__ void k_v0(const float* __restrict__ x) {
    int t = blockIdx.x * blockDim.x + threadIdx.x;
    if (t >= Bsz * Cn) return;
    const int b = t >> 4, c = t & 15;
    float s[16], n2 = 0.f;
#pragma unroll
    for (int o = 0; o < 16; o++) {
        float acc = 0.f;
#pragma unroll
        for (int i = 0; i < 16; i++)
            acc = fmaf(g_Wsum[(c * 16 + o) * 16 + i], x[(b * Cn + c) * 16 + i], acc);
        acc *= (1.f / (float)Rn);
        s[o] = acc; n2 += acc * acc;
    }
    const float norm = sqrtf(n2);
    const float sc = norm / (1.f + n2);
#pragma unroll
    for (int o = 0; o < 16; o++) g_v0[t * 16 + o] = sc * s[o];
}

// ---------------- K3: fused routing pass (HMMA, packed fp16 W) -------------
// Per warp, per r: 1x LDG.128 (B frags ready-made) -> 4x mma.m16n8k16
// -> logit quad-reduce -> exp -> accumulate s / sumexp in registers.
// grid (Rn/RBLK, Cn), block 256.
__global__ __launch_bounds__(256, 3) void k_route_mma(const float* __restrict__ x,
                                                      const float* __restrict__ vsrc) {
    const int c    = blockIdx.y;
    const int tid  = threadIdx.x;
    const int wid  = tid >> 5;
    const int lane = tid & 31;
    const int g    = lane >> 2;
    const int tg   = lane & 3;

    // ---- A fragments from x (fp32 -> fp16). M dim = b, K dim = i. ----
    uint32_t A[8];
#pragma unroll
    for (int mt = 0; mt < 2; mt++) {
        const int b_lo = g + mt * 16, b_hi = g + 8 + mt * 16;
#pragma unroll
        for (int kh = 0; kh < 2; kh++) {
            float2 lo = *reinterpret_cast<const float2*>(&x[(b_lo * Cn + c) * 16 + 2 * tg + kh * 8]);
            float2 hi = *reinterpret_cast<const float2*>(&x[(b_hi * Cn + c) * 16 + 2 * tg + kh * 8]);
            A[mt * 4 + kh * 2 + 0] = packh2(lo.x, lo.y);
            A[mt * 4 + kh * 2 + 1] = packh2(hi.x, hi.y);
        }
    }

    // ---- v values for this lane's 16 (b,o) positions ----
    // b(bi) = g + 8*bi ; o(oj) = 2*tg + (oj&1) + 8*(oj>>1)
    float vv[16];
#pragma unroll
    for (int bi = 0; bi < 4; bi++) {
        const int b = g + 8 * bi;
#pragma unroll
        for (int oj = 0; oj < 4; oj++) {
            const int o = 2 * tg + (oj & 1) + 8 * (oj >> 1);
            vv[bi * 4 + oj] = vsrc[(b * Cn + c) * 16 + o];
        }
    }

    float acc[16], esum[4];
#pragma unroll
    for (int j = 0; j < 16; j++) acc[j] = 0.f;
#pragma unroll
    for (int j = 0; j < 4; j++) esum[j] = 0.f;

    const int r0 = blockIdx.x * RBLK + wid * RPW;
    const uint4* __restrict__ Wp = g_Wh4 + ((size_t)c * Rn + r0) * 32 + lane;

#pragma unroll 4
    for (int k = 0; k < RPW; k++) {
        const uint4 cur = Wp[k * 32];
        float d[16];
        mma16816(d + 0,  A,     cur.x, cur.y);   // b 0-15,  o 0-7
        mma16816(d + 4,  A,     cur.z, cur.w);   // b 0-15,  o 8-15
        mma16816(d + 8,  A + 4, cur.x, cur.y);   // b 16-31, o 0-7
        mma16816(d + 12, A + 4, cur.z, cur.w);   // b 16-31, o 8-15
        // u[bi][oj] = d[(bi>>1)*8 + (oj>>1)*4 + (bi&1)*2 + (oj&1)]

        float p[4];
#pragma unroll
        for (int bi = 0; bi < 4; bi++) {
            float s = 0.f;
#pragma unroll
            for (int oj = 0; oj < 4; oj++) {
                const int di = ((bi >> 1) << 3) + ((oj >> 1) << 2) + ((bi & 1) << 1) + (oj & 1);
                s = fmaf(d[di], vv[bi * 4 + oj], s);
            }
            p[bi] = s;
        }
#pragma unroll
        for (int bi = 0; bi < 4; bi++) {
            p[bi] += __shfl_xor_sync(0xffffffffu, p[bi], 1);
            p[bi] += __shfl_xor_sync(0xffffffffu, p[bi], 2);
        }
#pragma unroll
        for (int bi = 0; bi < 4; bi++) {
            const float w = __expf(p[bi]);
            esum[bi] += w;
#pragma unroll
            for (int oj = 0; oj < 4; oj++) {
                const int di = ((bi >> 1) << 3) + ((oj >> 1) << 2) + ((bi & 1) << 1) + (oj & 1);
                acc[bi * 4 + oj] = fmaf(w, d[di], acc[bi * 4 + oj]);
            }
        }
    }

    // ---- block reduction: plain STS (transposed, conflict-free) + LDS tree ----
    __shared__ float s_acc[WARPS][16][32];
    __shared__ float s_es[WARPS][32];
#pragma unroll
    for (int j = 0; j < 16; j++) s_acc[wid][j][lane] = acc[j];
    if (tg == 0) {
#pragma unroll
        for (int bi = 0; bi < 4; bi++) s_es[wid][g + 8 * bi] = esum[bi];
    }
    __syncthreads();

#pragma unroll
    for (int pass = 0; pass < 2; pass++) {
        const int j  = (tid >> 5) + 8 * pass;
        const int ln = tid & 31;
        float s = 0.f;
#pragma unroll
        for (int w2 = 0; w2 < WARPS; w2++) s += s_acc[w2][j][ln];
        const int b = (ln >> 2) + ((j >> 2) << 3);
        const int o = ((ln & 3) << 1) + (j & 1) + ((j >> 1) & 1) * 8;
        atomicAdd(&g_sraw[(b * Cn + c) * 16 + o], s);
    }
    if (tid < 32) {
        float s = 0.f;
#pragma unroll
        for (int w2 = 0; w2 < WARPS; w2++) s += s_es[w2][tid];
        atomicAdd(&g_sumexp[tid * Cn + c], s);
    }
}

// ---------------- K4: v1 = squash(s1), vsum = v0+v1, reset accumulators ----
__global__ void k_v1() {
    int t = blockIdx.x * blockDim.x + threadIdx.x;
    if (t >= Bsz * Cn) return;
    const float inv = 1.f / g_sumexp[t];
    float s[16], n2 = 0.f;
#pragma unroll
    for (int o = 0; o < 16; o++) { s[o] = g_sraw[t * 16 + o] * inv; n2 += s[o] * s[o]; }
    const float norm = sqrtf(n2);
    const float sc = norm / (1.f + n2);
#pragma unroll
    for (int o = 0; o < 16; o++) {
        g_vsum[t * 16 + o] = g_v0[t * 16 + o] + sc * s[o];
        g_sraw[t * 16 + o] = 0.f;
    }
    g_sumexp[t] = 0.f;
}

// ---------------- K5: out = squash(s2) --------------------------------------
__global__ void k_out(float* __restrict__ out) {
    int t = blockIdx.x * blockDim.x + threadIdx.x;
    if (t >= Bsz * Cn) return;
    const float inv = 1.f / g_sumexp[t];
    float s[16], n2 = 0.f;
#pragma unroll
    for (int o = 0; o < 16; o++) { s[o] = g_sraw[t * 16 + o] * inv; n2 += s[o] * s[o]; }
    const float norm = sqrtf(n2);
    const float sc = norm / (1.f + n2);
#pragma unroll
    for (int o = 0; o < 16; o++) out[t * 16 + o] = sc * s[o];
}

// ---------------- launch ----------------------------------------------------
extern "C" void kernel_launch(void* const* d_in, const int* in_sizes, int n_in,
                              void* d_out, int out_size) {
    const float* x = (const float*)d_in[0];
    const float* W = (const float*)d_in[1];
    if (n_in >= 2 && in_sizes[0] > in_sizes[1]) {  // safety: x is 8192, W is 67M
        x = (const float*)d_in[1];
        W = (const float*)d_in[0];
    }
    float* out = (float*)d_out;

    float* d_v0   = nullptr;
    float* d_vsum = nullptr;
    cudaGetSymbolAddress((void**)&d_v0,   g_v0);
    cudaGetSymbolAddress((void**)&d_vsum, g_vsum);

    k_zero<<<32, 256>>>();
    k_prep<<<dim3(Rn / PR, Cn), 256>>>(W);
    k_v0<<<2, 256>>>(x);

    // iteration 1 (uses v0)
    k_route_mma<<<dim3(Rn / RBLK, Cn), 256>>>(x, d_v0);
    k_v1<<<2, 256>>>();

    // iteration 2 (uses v0+v1)
    k_route_mma<<<dim3(Rn / RBLK, Cn), 256>>>(x, d_vsum);
    k_out<<<2, 256>>>(out);
}

// round 6
// speedup vs baseline: 2.3281x; 1.1582x over previous
#include <cuda_runtime.h>
#include <cuda_fp16.h>
#include <cstdint>
#include <cstddef>

// Problem constants
#define Bsz  32
#define Rn   16384
#define Cn   16
#define Od   16

#define WARPS 8
#define PAIRS 4                   // warp pairs per block (route)
#define RPW   64                  // r per warp-pair in route
#define RBLK  (PAIRS * RPW)       // 256 r per block
#define PRPW  32                  // r per warp in prep
#define PRBLK (WARPS * PRPW)      // 256 r per prep block

// ---------------- scratch (device globals; no allocation allowed) ----------
__device__ uint4 g_Wh4[(size_t)Rn * Cn * 32];   // 134 MB fp16 W, fragment-packed
__device__ float g_Wsum[Cn * 256];              // sum over r of W  [c][o][i]
__device__ float g_v0[Bsz * Cn * Od];
__device__ float g_vsum[Bsz * Cn * Od];         // v0 + v1
__device__ float g_sraw[Bsz * Cn * Od];         // un-normalized weighted sums
__device__ float g_sumexp[Bsz * Cn];            // sum of exp(logit) per (b,c)

// ---------------- helpers ---------------------------------------------------
__device__ __forceinline__ uint32_t packh2(float a, float b) {
    __half2 h = __floats2half2_rn(a, b);
    return *reinterpret_cast<uint32_t*>(&h);
}

__device__ __forceinline__ void mma16816(float* d, const uint32_t* a,
                                         uint32_t b0, uint32_t b1) {
    asm volatile(
        "mma.sync.aligned.m16n8k16.row.col.f32.f16.f16.f32 "
        "{%0,%1,%2,%3}, {%4,%5,%6,%7}, {%8,%9}, {%10,%11,%12,%13};\n"
        : "=f"(d[0]), "=f"(d[1]), "=f"(d[2]), "=f"(d[3])
        : "r"(a[0]), "r"(a[1]), "r"(a[2]), "r"(a[3]),
          "r"(b0), "r"(b1),
          "f"(0.f), "f"(0.f), "f"(0.f), "f"(0.f));
}

// ---------------- K0: zero accumulators (per replay) -----------------------
__global__ void k_zero() {
    int i = blockIdx.x * blockDim.x + threadIdx.x;
    if (i < Cn * 256)       g_Wsum[i] = 0.f;
    if (i < Bsz * Cn * Od)  g_sraw[i] = 0.f;
    if (i < Bsz * Cn)       g_sumexp[i] = 0.f;
}

// ---------------- K1: prep — convert W to packed fp16 frags + Wsum ---------
// Direct loads in fragment order (no smem staging). Lane l (g=l>>2, tg=l&3)
// loads W[o=g][2tg..], W[g][2tg+8..], W[g+8][2tg..], W[g+8][2tg+8..] as float2,
// packs to uint4, stores to g_Wh4[(c*Rn+r)*32 + l]. Wsum accumulated in regs.
__global__ __launch_bounds__(256) void k_prep(const float* __restrict__ W) {
    const int c    = blockIdx.y;
    const int tid  = threadIdx.x;
    const int wid  = tid >> 5;
    const int lane = tid & 31;
    const int g    = lane >> 2;
    const int tg   = lane & 3;
    const int r0   = blockIdx.x * PRBLK + wid * PRPW;

    float ws[8];
#pragma unroll
    for (int j = 0; j < 8; j++) ws[j] = 0.f;

#pragma unroll 4
    for (int k = 0; k < PRPW; k++) {
        const float2* row = reinterpret_cast<const float2*>(
            &W[((size_t)(r0 + k) * Cn + c) * 256]);
        float2 f0 = row[g * 8 + tg];
        float2 f1 = row[g * 8 + tg + 4];
        float2 f2 = row[(g + 8) * 8 + tg];
        float2 f3 = row[(g + 8) * 8 + tg + 4];
        ws[0] += f0.x; ws[1] += f0.y; ws[2] += f1.x; ws[3] += f1.y;
        ws[4] += f2.x; ws[5] += f2.y; ws[6] += f3.x; ws[7] += f3.y;
        uint4 o;
        o.x = packh2(f0.x, f0.y); o.y = packh2(f1.x, f1.y);
        o.z = packh2(f2.x, f2.y); o.w = packh2(f3.x, f3.y);
        g_Wh4[((size_t)c * Rn + (r0 + k)) * 32 + lane] = o;
    }

    // fold Wsum partials: positions per lane are a bijection onto 0..255
    __shared__ float s_ws[WARPS][256];
    const int p0 = g * 16 + 2 * tg;        // (o=g,   i=2tg)
    const int p2 = (g + 8) * 16 + 2 * tg;  // (o=g+8, i=2tg)
    s_ws[wid][p0]     = ws[0]; s_ws[wid][p0 + 1] = ws[1];
    s_ws[wid][p0 + 8] = ws[2]; s_ws[wid][p0 + 9] = ws[3];
    s_ws[wid][p2]     = ws[4]; s_ws[wid][p2 + 1] = ws[5];
    s_ws[wid][p2 + 8] = ws[6]; s_ws[wid][p2 + 9] = ws[7];
    __syncthreads();
    float s = 0.f;
#pragma unroll
    for (int w = 0; w < WARPS; w++) s += s_ws[w][tid];
    atomicAdd(&g_Wsum[c * 256 + tid], s);
}

// ---------------- K2: v0 = squash((1/R) * Wsum . x) ------------------------
__global__ void k_v0(const float* __restrict__ x) {
    int t = blockIdx.x * blockDim.x + threadIdx.x;
    if (t >= Bsz * Cn) return;
    const int b = t >> 4, c = t & 15;
    float s[16], n2 = 0.f;
#pragma unroll
    for (int o = 0; o < 16; o++) {
        float acc = 0.f;
#pragma unroll
        for (int i = 0; i < 16; i++)
            acc = fmaf(g_Wsum[(c * 16 + o) * 16 + i], x[(b * Cn + c) * 16 + i], acc);
        acc *= (1.f / (float)Rn);
        s[o] = acc; n2 += acc * acc;
    }
    const float norm = sqrtf(n2);
    const float sc = norm / (1.f + n2);
#pragma unroll
    for (int o = 0; o < 16; o++) g_v0[t * 16 + o] = sc * s[o];
}

// ---------------- K3: fused routing pass (HMMA, b split across warp pairs) --
// Warp pair (2q, 2q+1) processes the same r-range; parity pb selects b-half
// (pb*16 .. pb*16+15). Per warp per r: 1 LDG.128 (L1-hit for odd warp),
// 2x mma.m16n8k16, logit quad-reduce, exp, accumulate.
__global__ __launch_bounds__(256, 4) void k_route_mma(const float* __restrict__ x,
                                                      const float* __restrict__ vsrc) {
    const int c    = blockIdx.y;
    const int tid  = threadIdx.x;
    const int wid  = tid >> 5;
    const int lane = tid & 31;
    const int g    = lane >> 2;
    const int tg   = lane & 3;
    const int pair = wid >> 1;
    const int pb   = wid & 1;     // b-half: 0 -> b 0-15, 1 -> b 16-31

    // ---- A fragments from x (fp32 -> fp16), M = 16 b's of this half ----
    uint32_t A[4];
    {
        const int b_lo = pb * 16 + g, b_hi = pb * 16 + 8 + g;
#pragma unroll
        for (int kh = 0; kh < 2; kh++) {
            float2 lo = *reinterpret_cast<const float2*>(&x[(b_lo * Cn + c) * 16 + 2 * tg + kh * 8]);
            float2 hi = *reinterpret_cast<const float2*>(&x[(b_hi * Cn + c) * 16 + 2 * tg + kh * 8]);
            A[kh * 2 + 0] = packh2(lo.x, lo.y);
            A[kh * 2 + 1] = packh2(hi.x, hi.y);
        }
    }

    // ---- v for this lane's 8 (b,o) positions ----
    // b(bi) = pb*16 + g + 8*bi ; o(oj) = 2*tg + (oj&1) + 8*(oj>>1)
    float vv[8];
#pragma unroll
    for (int bi = 0; bi < 2; bi++) {
        const int b = pb * 16 + g + 8 * bi;
#pragma unroll
        for (int oj = 0; oj < 4; oj++) {
            const int o = 2 * tg + (oj & 1) + 8 * (oj >> 1);
            vv[bi * 4 + oj] = vsrc[(b * Cn + c) * 16 + o];
        }
    }

    float acc[8], esum[2];
#pragma unroll
    for (int j = 0; j < 8; j++) acc[j] = 0.f;
    esum[0] = esum[1] = 0.f;

    const int r0 = blockIdx.x * RBLK + pair * RPW;
    const uint4* __restrict__ Wp = g_Wh4 + ((size_t)c * Rn + r0) * 32 + lane;

#pragma unroll 4
    for (int k = 0; k < RPW; k++) {
        const uint4 cur = Wp[k * 32];
        float d[8];
        mma16816(d + 0, A, cur.x, cur.y);   // o 0-7
        mma16816(d + 4, A, cur.z, cur.w);   // o 8-15
        // u[bi][oj] = d[(oj>>1)*4 + 2*bi + (oj&1)]

        float p[2];
#pragma unroll
        for (int bi = 0; bi < 2; bi++) {
            float s = 0.f;
#pragma unroll
            for (int oj = 0; oj < 4; oj++) {
                const int di = ((oj >> 1) << 2) + (bi << 1) + (oj & 1);
                s = fmaf(d[di], vv[bi * 4 + oj], s);
            }
            p[bi] = s;
        }
#pragma unroll
        for (int bi = 0; bi < 2; bi++) {
            p[bi] += __shfl_xor_sync(0xffffffffu, p[bi], 1);
            p[bi] += __shfl_xor_sync(0xffffffffu, p[bi], 2);
        }
#pragma unroll
        for (int bi = 0; bi < 2; bi++) {
            const float w = __expf(p[bi]);
            esum[bi] += w;
#pragma unroll
            for (int oj = 0; oj < 4; oj++) {
                const int di = ((oj >> 1) << 2) + (bi << 1) + (oj & 1);
                acc[bi * 4 + oj] = fmaf(w, d[di], acc[bi * 4 + oj]);
            }
        }
    }

    // ---- block reduction ----
    __shared__ float s_acc[WARPS][8][32];
    __shared__ float s_es[WARPS][16];
#pragma unroll
    for (int j = 0; j < 8; j++) s_acc[wid][j][lane] = acc[j];
    if (tg == 0) {
        s_es[wid][g]     = esum[0];
        s_es[wid][g + 8] = esum[1];
    }
    __syncthreads();

#pragma unroll
    for (int pass = 0; pass < 2; pass++) {
        const int cell = pass * 256 + tid;      // 9 bits: pb(1) j(3) lane(5)
        const int cpb  = (cell >> 8) & 1;
        const int j    = (cell >> 5) & 7;
        const int ln   = cell & 31;
        float s = 0.f;
#pragma unroll
        for (int q = 0; q < PAIRS; q++) s += s_acc[2 * q + cpb][j][ln];
        const int b = (ln >> 2) + 8 * (j >> 2) + 16 * cpb;
        const int o = ((ln & 3) << 1) + (j & 1) + 8 * ((j >> 1) & 1);
        atomicAdd(&g_sraw[(b * Cn + c) * 16 + o], s);
    }
    if (tid < 32) {
        const int cpb = tid >> 4;
        float s = 0.f;
#pragma unroll
        for (int q = 0; q < PAIRS; q++) s += s_es[2 * q + cpb][tid & 15];
        atomicAdd(&g_sumexp[tid * Cn + c], s);
    }
}

// ---------------- K4: v1 = squash(s1), vsum = v0+v1, reset accumulators ----
__global__ void k_v1() {
    int t = blockIdx.x * blockDim.x + threadIdx.x;
    if (t >= Bsz * Cn) return;
    const float inv = 1.f / g_sumexp[t];
    float s[16], n2 = 0.f;
#pragma unroll
    for (int o = 0; o < 16; o++) { s[o] = g_sraw[t * 16 + o] * inv; n2 += s[o] * s[o]; }
    const float norm = sqrtf(n2);
    const float sc = norm / (1.f + n2);
#pragma unroll
    for (int o = 0; o < 16; o++) {
        g_vsum[t * 16 + o] = g_v0[t * 16 + o] + sc * s[o];
        g_sraw[t * 16 + o] = 0.f;
    }
    g_sumexp[t] = 0.f;
}

// ---------------- K5: out = squash(s2) --------------------------------------
__global__ void k_out(float* __restrict__ out) {
    int t = blockIdx.x * blockDim.x + threadIdx.x;
    if (t >= Bsz * Cn) return;
    const float inv = 1.f / g_sumexp[t];
    float s[16], n2 = 0.f;
#pragma unroll
    for (int o = 0; o < 16; o++) { s[o] = g_sraw[t * 16 + o] * inv; n2 += s[o] * s[o]; }
    const float norm = sqrtf(n2);
    const float sc = norm / (1.f + n2);
#pragma unroll
    for (int o = 0; o < 16; o++) out[t * 16 + o] = sc * s[o];
}

// ---------------- launch ----------------------------------------------------
extern "C" void kernel_launch(void* const* d_in, const int* in_sizes, int n_in,
                              void* d_out, int out_size) {
    const float* x = (const float*)d_in[0];
    const float* W = (const float*)d_in[1];
    if (n_in >= 2 && in_sizes[0] > in_sizes[1]) {  // safety: x is 8192, W is 67M
        x = (const float*)d_in[1];
        W = (const float*)d_in[0];
    }
    float* out = (float*)d_out;

    float* d_v0   = nullptr;
    float* d_vsum = nullptr;
    cudaGetSymbolAddress((void**)&d_v0,   g_v0);
    cudaGetSymbolAddress((void**)&d_vsum, g_vsum);

    k_zero<<<32, 256>>>();
    k_prep<<<dim3(Rn / PRBLK, Cn), 256>>>(W);
    k_v0<<<2, 256>>>(x);

    // iteration 1 (uses v0)
    k_route_mma<<<dim3(Rn / RBLK, Cn), 256>>>(x, d_v0);
    k_v1<<<2, 256>>>();

    // iteration 2 (uses v0+v1)
    k_route_mma<<<dim3(Rn / RBLK, Cn), 256>>>(x, d_vsum);
    k_out<<<2, 256>>>(out);
}

// round 7
// speedup vs baseline: 2.3929x; 1.0278x over previous
#include <cuda_runtime.h>
#include <cuda_fp16.h>
#include <cstdint>
#include <cstddef>

// Problem constants
#define Bsz  32
#define Rn   16384
#define Cn   16
#define Od   16

#define WARPS 8
#define PAIRS 4                   // warp pairs per block (route)
#define RPW   64                  // r per warp-pair in route
#define RBLK  (PAIRS * RPW)       // 256 r per block
#define PRPW  32                  // r per warp in prep
#define PRBLK (WARPS * PRPW)      // 256 r per prep block

// ---------------- scratch (device globals; no allocation allowed) ----------
// +32 pad: route prefetch reads one uint4 row past the end harmlessly.
__device__ uint4 g_Wh4[(size_t)Rn * Cn * 32 + 32];  // 134 MB fp16 W, frag-packed
__device__ float g_Wsum[Cn * 256];              // sum over r of W  [c][o][i]
__device__ float g_v0[Bsz * Cn * Od];
__device__ float g_vsum[Bsz * Cn * Od];         // v0 + v1
__device__ float g_sraw[Bsz * Cn * Od];         // un-normalized weighted sums
__device__ float g_sumexp[Bsz * Cn];            // sum of exp(logit) per (b,c)

// ---------------- helpers ---------------------------------------------------
__device__ __forceinline__ uint32_t packh2(float a, float b) {
    __half2 h = __floats2half2_rn(a, b);
    return *reinterpret_cast<uint32_t*>(&h);
}

union F2U { float2 f; unsigned long long u; };

__device__ __forceinline__ float2 ffma2(float2 a, float2 b, float2 c) {
    F2U A, B, C, D; A.f = a; B.f = b; C.f = c;
    asm("fma.rn.f32x2 %0, %1, %2, %3;" : "=l"(D.u) : "l"(A.u), "l"(B.u), "l"(C.u));
    return D.f;
}
__device__ __forceinline__ float2 fmul2(float2 a, float2 b) {
    F2U A, B, D; A.f = a; B.f = b;
    asm("mul.rn.f32x2 %0, %1, %2;" : "=l"(D.u) : "l"(A.u), "l"(B.u));
    return D.f;
}

// mma m16n8k16: dA = rows g (b-low), dB = rows g+8 (b-high), cols = 2 o's
__device__ __forceinline__ void mma16816(float2& dA, float2& dB, const uint32_t* a,
                                         uint32_t b0, uint32_t b1) {
    asm volatile(
        "mma.sync.aligned.m16n8k16.row.col.f32.f16.f16.f32 "
        "{%0,%1,%2,%3}, {%4,%5,%6,%7}, {%8,%9}, {%10,%11,%12,%13};\n"
        : "=f"(dA.x), "=f"(dA.y), "=f"(dB.x), "=f"(dB.y)
        : "r"(a[0]), "r"(a[1]), "r"(a[2]), "r"(a[3]),
          "r"(b0), "r"(b1),
          "f"(0.f), "f"(0.f), "f"(0.f), "f"(0.f));
}

// ---------------- K0: zero accumulators (per replay) -----------------------
__global__ void k_zero() {
    int i = blockIdx.x * blockDim.x + threadIdx.x;
    if (i < Cn * 256)       g_Wsum[i] = 0.f;
    if (i < Bsz * Cn * Od)  g_sraw[i] = 0.f;
    if (i < Bsz * Cn)       g_sumexp[i] = 0.f;
}

// ---------------- K1: prep — convert W to packed fp16 frags + Wsum ---------
__global__ __launch_bounds__(256) void k_prep(const float* __restrict__ W) {
    const int c    = blockIdx.y;
    const int tid  = threadIdx.x;
    const int wid  = tid >> 5;
    const int lane = tid & 31;
    const int g    = lane >> 2;
    const int tg   = lane & 3;
    const int r0   = blockIdx.x * PRBLK + wid * PRPW;

    float ws[8];
#pragma unroll
    for (int j = 0; j < 8; j++) ws[j] = 0.f;

#pragma unroll 8
    for (int k = 0; k < PRPW; k++) {
        const float2* row = reinterpret_cast<const float2*>(
            &W[((size_t)(r0 + k) * Cn + c) * 256]);
        float2 f0 = __ldcs(&row[g * 8 + tg]);
        float2 f1 = __ldcs(&row[g * 8 + tg + 4]);
        float2 f2 = __ldcs(&row[(g + 8) * 8 + tg]);
        float2 f3 = __ldcs(&row[(g + 8) * 8 + tg + 4]);
        ws[0] += f0.x; ws[1] += f0.y; ws[2] += f1.x; ws[3] += f1.y;
        ws[4] += f2.x; ws[5] += f2.y; ws[6] += f3.x; ws[7] += f3.y;
        uint4 o;
        o.x = packh2(f0.x, f0.y); o.y = packh2(f1.x, f1.y);
        o.z = packh2(f2.x, f2.y); o.w = packh2(f3.x, f3.y);
        __stcs(&g_Wh4[((size_t)c * Rn + (r0 + k)) * 32 + lane], o);
    }

    // fold Wsum partials: positions per lane are a bijection onto 0..255
    __shared__ float s_ws[WARPS][256];
    const int p0 = g * 16 + 2 * tg;        // (o=g,   i=2tg)
    const int p2 = (g + 8) * 16 + 2 * tg;  // (o=g+8, i=2tg)
    s_ws[wid][p0]     = ws[0]; s_ws[wid][p0 + 1] = ws[1];
    s_ws[wid][p0 + 8] = ws[2]; s_ws[wid][p0 + 9] = ws[3];
    s_ws[wid][p2]     = ws[4]; s_ws[wid][p2 + 1] = ws[5];
    s_ws[wid][p2 + 8] = ws[6]; s_ws[wid][p2 + 9] = ws[7];
    __syncthreads();
    float s = 0.f;
#pragma unroll
    for (int w = 0; w < WARPS; w++) s += s_ws[w][tid];
    atomicAdd(&g_Wsum[c * 256 + tid], s);
}

// ---------------- K2: v0 = squash((1/R) * Wsum . x) ------------------------
__global__ void k_v0(const float* __restrict__ x) {
    int t = blockIdx.x * blockDim.x + threadIdx.x;
    if (t >= Bsz * Cn) return;
    const int b = t >> 4, c = t & 15;
    float s[16], n2 = 0.f;
#pragma unroll
    for (int o = 0; o < 16; o++) {
        float acc = 0.f;
#pragma unroll
        for (int i = 0; i < 16; i++)
            acc = fmaf(g_Wsum[(c * 16 + o) * 16 + i], x[(b * Cn + c) * 16 + i], acc);
        acc *= (1.f / (float)Rn);
        s[o] = acc; n2 += acc * acc;
    }
    const float norm = sqrtf(n2);
    const float sc = norm / (1.f + n2);
#pragma unroll
    for (int o = 0; o < 16; o++) g_v0[t * 16 + o] = sc * s[o];
}

// ---------------- K3: fused routing pass (HMMA, b split across warp pairs) --
// Warp pair (2q, 2q+1) processes the same r-range; parity pb selects b-half.
// Per warp per r: 1 LDG.128 (prefetched), 2x mma.m16n8k16, packed f32x2
// logit dot, 4 SHFL, 2 exp, packed f32x2 accumulation.
__global__ __launch_bounds__(256, 4) void k_route_mma(const float* __restrict__ x,
                                                      const float* __restrict__ vsrc) {
    const int c    = blockIdx.y;
    const int tid  = threadIdx.x;
    const int wid  = tid >> 5;
    const int lane = tid & 31;
    const int g    = lane >> 2;
    const int tg   = lane & 3;
    const int pair = wid >> 1;
    const int pb   = wid & 1;     // b-half: 0 -> b 0-15, 1 -> b 16-31

    // ---- A fragments from x (fp32 -> fp16), M = 16 b's of this half ----
    uint32_t A[4];
    {
        const int b_lo = pb * 16 + g, b_hi = pb * 16 + 8 + g;
#pragma unroll
        for (int kh = 0; kh < 2; kh++) {
            float2 lo = *reinterpret_cast<const float2*>(&x[(b_lo * Cn + c) * 16 + 2 * tg + kh * 8]);
            float2 hi = *reinterpret_cast<const float2*>(&x[(b_hi * Cn + c) * 16 + 2 * tg + kh * 8]);
            A[kh * 2 + 0] = packh2(lo.x, lo.y);
            A[kh * 2 + 1] = packh2(hi.x, hi.y);
        }
    }

    // ---- v pairs for this lane's (b,o) positions ----
    // vv2[0],vv2[1]: b_lo, o pairs (2tg,2tg+1) and (2tg+8,2tg+9)
    // vv2[2],vv2[3]: b_hi, same o pairs
    float2 vv2[4];
    {
        const int b_lo = pb * 16 + g, b_hi = pb * 16 + 8 + g;
        vv2[0] = *reinterpret_cast<const float2*>(&vsrc[(b_lo * Cn + c) * 16 + 2 * tg]);
        vv2[1] = *reinterpret_cast<const float2*>(&vsrc[(b_lo * Cn + c) * 16 + 2 * tg + 8]);
        vv2[2] = *reinterpret_cast<const float2*>(&vsrc[(b_hi * Cn + c) * 16 + 2 * tg]);
        vv2[3] = *reinterpret_cast<const float2*>(&vsrc[(b_hi * Cn + c) * 16 + 2 * tg + 8]);
    }

    float2 acc2[4];
#pragma unroll
    for (int j = 0; j < 4; j++) acc2[j] = make_float2(0.f, 0.f);
    float esum0 = 0.f, esum1 = 0.f;

    const int r0 = blockIdx.x * RBLK + pair * RPW;
    const uint4* __restrict__ Wq = g_Wh4 + ((size_t)c * Rn + r0) * 32 + lane;

    uint4 nxt = *Wq;
#pragma unroll 4
    for (int k = 0; k < RPW; k++) {
        const uint4 cur = nxt;
        Wq += 32;
        nxt = *Wq;   // last iter reads 1 row past (padded) — harmless

        float2 dA1, dB1, dA2, dB2;
        mma16816(dA1, dB1, A, cur.x, cur.y);   // o 0-7   (dA=b_lo, dB=b_hi)
        mma16816(dA2, dB2, A, cur.z, cur.w);   // o 8-15

        // logit partials (each lane: its 4 o's), packed f32x2
        float2 q0 = ffma2(dA2, vv2[1], fmul2(dA1, vv2[0]));
        float2 q1 = ffma2(dB2, vv2[3], fmul2(dB1, vv2[2]));
        float p0 = q0.x + q0.y;
        float p1 = q1.x + q1.y;
        p0 += __shfl_xor_sync(0xffffffffu, p0, 1);
        p0 += __shfl_xor_sync(0xffffffffu, p0, 2);
        p1 += __shfl_xor_sync(0xffffffffu, p1, 1);
        p1 += __shfl_xor_sync(0xffffffffu, p1, 2);

        const float w0 = __expf(p0);
        const float w1 = __expf(p1);
        esum0 += w0; esum1 += w1;
        const float2 w02 = make_float2(w0, w0);
        const float2 w12 = make_float2(w1, w1);
        acc2[0] = ffma2(w02, dA1, acc2[0]);
        acc2[1] = ffma2(w02, dA2, acc2[1]);
        acc2[2] = ffma2(w12, dB1, acc2[2]);
        acc2[3] = ffma2(w12, dB2, acc2[3]);
    }

    // ---- block reduction ----
    // j semantics: j = bi*4 + oj ; bi0=b_lo, bi1=b_hi ; oj -> o = 2tg+(oj&1)+8*(oj>>1)
    __shared__ float s_acc[WARPS][8][32];
    __shared__ float s_es[WARPS][16];
    s_acc[wid][0][lane] = acc2[0].x; s_acc[wid][1][lane] = acc2[0].y;
    s_acc[wid][2][lane] = acc2[1].x; s_acc[wid][3][lane] = acc2[1].y;
    s_acc[wid][4][lane] = acc2[2].x; s_acc[wid][5][lane] = acc2[2].y;
    s_acc[wid][6][lane] = acc2[3].x; s_acc[wid][7][lane] = acc2[3].y;
    if (tg == 0) {
        s_es[wid][g]     = esum0;
        s_es[wid][g + 8] = esum1;
    }
    __syncthreads();

#pragma unroll
    for (int pass = 0; pass < 2; pass++) {
        const int cell = pass * 256 + tid;      // 9 bits: pb(1) j(3) lane(5)
        const int cpb  = (cell >> 8) & 1;
        const int j    = (cell >> 5) & 7;
        const int ln   = cell & 31;
        float s = 0.f;
#pragma unroll
        for (int q = 0; q < PAIRS; q++) s += s_acc[2 * q + cpb][j][ln];
        const int b = (ln >> 2) + 8 * (j >> 2) + 16 * cpb;
        const int o = ((ln & 3) << 1) + (j & 1) + 8 * ((j >> 1) & 1);
        atomicAdd(&g_sraw[(b * Cn + c) * 16 + o], s);
    }
    if (tid < 32) {
        const int cpb = tid >> 4;
        float s = 0.f;
#pragma unroll
        for (int q = 0; q < PAIRS; q++) s += s_es[2 * q + cpb][tid & 15];
        atomicAdd(&g_sumexp[tid * Cn + c], s);
    }
}

// ---------------- K4: v1 = squash(s1), vsum = v0+v1, reset accumulators ----
__global__ void k_v1() {
    int t = blockIdx.x * blockDim.x + threadIdx.x;
    if (t >= Bsz * Cn) return;
    const float inv = 1.f / g_sumexp[t];
    float s[16], n2 = 0.f;
#pragma unroll
    for (int o = 0; o < 16; o++) { s[o] = g_sraw[t * 16 + o] * inv; n2 += s[o] * s[o]; }
    const float norm = sqrtf(n2);
    const float sc = norm / (1.f + n2);
#pragma unroll
    for (int o = 0; o < 16; o++) {
        g_vsum[t * 16 + o] = g_v0[t * 16 + o] + sc * s[o];
        g_sraw[t * 16 + o] = 0.f;
    }
    g_sumexp[t] = 0.f;
}

// ---------------- K5: out = squash(s2) --------------------------------------
__global__ void k_out(float* __restrict__ out) {
    int t = blockIdx.x * blockDim.x + threadIdx.x;
    if (t >= Bsz * Cn) return;
    const float inv = 1.f / g_sumexp[t];
    float s[16], n2 = 0.f;
#pragma unroll
    for (int o = 0; o < 16; o++) { s[o] = g_sraw[t * 16 + o] * inv; n2 += s[o] * s[o]; }
    const float norm = sqrtf(n2);
    const float sc = norm / (1.f + n2);
#pragma unroll
    for (int o = 0; o < 16; o++) out[t * 16 + o] = sc * s[o];
}

// ---------------- launch ----------------------------------------------------
extern "C" void kernel_launch(void* const* d_in, const int* in_sizes, int n_in,
                              void* d_out, int out_size) {
    const float* x = (const float*)d_in[0];
    const float* W = (const float*)d_in[1];
    if (n_in >= 2 && in_sizes[0] > in_sizes[1]) {  // safety: x is 8192, W is 67M
        x = (const float*)d_in[1];
        W = (const float*)d_in[0];
    }
    float* out = (float*)d_out;

    float* d_v0   = nullptr;
    float* d_vsum = nullptr;
    cudaGetSymbolAddress((void**)&d_v0,   g_v0);
    cudaGetSymbolAddress((void**)&d_vsum, g_vsum);

    k_zero<<<32, 256>>>();
    k_prep<<<dim3(Rn / PRBLK, Cn), 256>>>(W);
    k_v0<<<2, 256>>>(x);

    // iteration 1 (uses v0)
    k_route_mma<<<dim3(Rn / RBLK, Cn), 256>>>(x, d_v0);
    k_v1<<<2, 256>>>();

    // iteration 2 (uses v0+v1)
    k_route_mma<<<dim3(Rn / RBLK, Cn), 256>>>(x, d_vsum);
    k_out<<<2, 256>>>(out);
}